// round 1
// baseline (speedup 1.0000x reference)
#include <cuda_runtime.h>

// Perona-Malik single diffusion step.
// image: [64, 1, 1024, 1024] fp32 in [0,1]
// out   = clamp(image + g * exp(-g^2/K^2) * dt, 0, 1)
// g     = 5-point Laplacian with ReflectionPad2d(1) (reflect, no edge dup)
// K = 0.1 -> 1/K^2 = 100 ; dt = 0.15

#define W 1024
#define H 1024
#define W4 (W / 4)

__global__ __launch_bounds__(256, 8)
void pm_kernel(const float* __restrict__ in, float* __restrict__ out) {
    const int y = blockIdx.x;          // row 0..1023
    const int n = blockIdx.y;          // image 0..N-1
    const int t = threadIdx.x;         // float4 column 0..255

    const float* img = in  + (size_t)n * (W * H);
    float*       o   = out + (size_t)n * (W * H);

    // reflect (no edge duplication): -1 -> 1, H -> H-2
    const int ym1 = (y == 0)     ? 1     : y - 1;
    const int yp1 = (y == H - 1) ? H - 2 : y + 1;

    const float4* rc = (const float4*)(img + (size_t)y   * W);
    const float4* ru = (const float4*)(img + (size_t)ym1 * W);
    const float4* rd = (const float4*)(img + (size_t)yp1 * W);

    const float4 c = rc[t];
    const float4 u = ru[t];
    const float4 d = rd[t];

    // horizontal halo (scalar; same cache lines as neighbors' float4 loads)
    const float* rowc = img + (size_t)y * W;
    const float left  = (t == 0)      ? rowc[1]         : rowc[4 * t - 1];
    const float right = (t == W4 - 1) ? rowc[W - 2]     : rowc[4 * t + 4];

    float4 g;
    g.x = u.x + d.x + left + c.y - 4.0f * c.x;
    g.y = u.y + d.y + c.x  + c.z - 4.0f * c.y;
    g.z = u.z + d.z + c.y  + c.w - 4.0f * c.z;
    g.w = u.w + d.w + c.z  + right - 4.0f * c.w;

    float4 r;
    {
        float gg, co, v;
        gg = g.x; co = __expf(-gg * gg * 100.0f);
        v = fmaf(gg * co, 0.15f, c.x); r.x = fminf(fmaxf(v, 0.0f), 1.0f);
        gg = g.y; co = __expf(-gg * gg * 100.0f);
        v = fmaf(gg * co, 0.15f, c.y); r.y = fminf(fmaxf(v, 0.0f), 1.0f);
        gg = g.z; co = __expf(-gg * gg * 100.0f);
        v = fmaf(gg * co, 0.15f, c.z); r.z = fminf(fmaxf(v, 0.0f), 1.0f);
        gg = g.w; co = __expf(-gg * gg * 100.0f);
        v = fmaf(gg * co, 0.15f, c.w); r.w = fminf(fmaxf(v, 0.0f), 1.0f);
    }

    float4* ro = (float4*)(o + (size_t)y * W);
    ro[t] = r;
}

extern "C" void kernel_launch(void* const* d_in, const int* in_sizes, int n_in,
                              void* d_out, int out_size) {
    const float* image = (const float*)d_in[0];
    // d_in[1] is the fixed 3x3 Laplace kernel; hardcoded in pm_kernel.
    float* out = (float*)d_out;

    const int n_images = in_sizes[0] / (W * H);   // 64
    dim3 grid(H, n_images);
    pm_kernel<<<grid, 256>>>(image, out);
}

// round 2
// speedup vs baseline: 1.1713x; 1.1713x over previous
#include <cuda_runtime.h>

// Perona-Malik single diffusion step, 4 rows per block, shuffle halos,
// streaming stores.
// out = clamp(image + g * exp(-g^2/K^2) * dt, 0, 1)
// g   = 5-point Laplacian with ReflectionPad2d(1); K=0.1 (1/K^2=100), dt=0.15

#define W 1024
#define H 1024
#define W4 (W / 4)
#define ROWS 4

__device__ __forceinline__ void stcs4(float4* p, float4 v) {
    asm volatile("st.global.cs.v4.f32 [%0], {%1,%2,%3,%4};"
                 :: "l"(p), "f"(v.x), "f"(v.y), "f"(v.z), "f"(v.w) : "memory");
}

__global__ __launch_bounds__(256, 6)
void pm_kernel(const float* __restrict__ in, float* __restrict__ out) {
    const int y0 = blockIdx.x * ROWS;      // first output row of this block
    const int n  = blockIdx.y;             // image index
    const int t  = threadIdx.x;            // float4 column 0..255
    const int lane = t & 31;

    const float* img = in  + (size_t)n * (W * H);
    float*       o   = out + (size_t)n * (W * H);

    // Load 6 rows: y0-1 .. y0+4, reflect at the volume edges (no edge dup).
    // Front-batched -> 6 consecutive LDG.128 per thread.
    float4 rr[ROWS + 2];
    #pragma unroll
    for (int i = 0; i < ROWS + 2; i++) {
        int yy = y0 - 1 + i;
        yy = (yy < 0) ? 1 : ((yy >= H) ? (2 * H - 2 - yy) : yy);
        rr[i] = ((const float4*)(img + (size_t)yy * W))[t];
    }

    #pragma unroll
    for (int i = 0; i < ROWS; i++) {
        const int y = y0 + i;
        const float4 u = rr[i];
        const float4 c = rr[i + 1];
        const float4 d = rr[i + 2];

        // Horizontal halo via warp shuffle; warp-edge lanes fall back to a
        // scalar global load (L1/L2 hit), image-edge lanes use reflection.
        float left  = __shfl_up_sync(0xffffffffu, c.w, 1);
        float right = __shfl_down_sync(0xffffffffu, c.x, 1);
        const float* rowc = img + (size_t)y * W;
        if (lane == 0)
            left  = (t == 0)      ? c.y : rowc[4 * t - 1];
        if (lane == 31)
            right = (t == W4 - 1) ? c.z : rowc[4 * t + 4];

        float4 g;
        g.x = u.x + d.x + left + c.y  - 4.0f * c.x;
        g.y = u.y + d.y + c.x  + c.z  - 4.0f * c.y;
        g.z = u.z + d.z + c.y  + c.w  - 4.0f * c.z;
        g.w = u.w + d.w + c.z  + right - 4.0f * c.w;

        float4 r;
        float gg, co, v;
        gg = g.x; co = __expf(-gg * gg * 100.0f);
        v = fmaf(gg * co, 0.15f, c.x); r.x = fminf(fmaxf(v, 0.0f), 1.0f);
        gg = g.y; co = __expf(-gg * gg * 100.0f);
        v = fmaf(gg * co, 0.15f, c.y); r.y = fminf(fmaxf(v, 0.0f), 1.0f);
        gg = g.z; co = __expf(-gg * gg * 100.0f);
        v = fmaf(gg * co, 0.15f, c.z); r.z = fminf(fmaxf(v, 0.0f), 1.0f);
        gg = g.w; co = __expf(-gg * gg * 100.0f);
        v = fmaf(gg * co, 0.15f, c.w); r.w = fminf(fmaxf(v, 0.0f), 1.0f);

        stcs4((float4*)(o + (size_t)y * W) + t, r);
    }
}

extern "C" void kernel_launch(void* const* d_in, const int* in_sizes, int n_in,
                              void* d_out, int out_size) {
    const float* image = (const float*)d_in[0];
    // d_in[1] is the fixed 3x3 Laplace kernel; hardcoded in pm_kernel.
    float* out = (float*)d_out;

    const int n_images = in_sizes[0] / (W * H);   // 64
    dim3 grid(H / ROWS, n_images);
    pm_kernel<<<grid, 256>>>(image, out);
}